// round 1
// baseline (speedup 1.0000x reference)
#include <cuda_runtime.h>
#include <math.h>
#include <stdint.h>

#define NB      16384
#define FANOUT  16
#define EMB     128
#define HID     256
#define NEDGE   16

#define MT      64      // events (rows) per block
#define KC      32      // k-chunk
#define APITCH  65      // padded pitch for A tile [k][m]
#define BPITCH  264     // padded pitch for B tile [k][n], multiple of 8 floats

// ---- persistent scratch (no allocations allowed) ----
__device__ float g_WsrcT [EMB*HID];
__device__ float g_WdstT [EMB*HID];
__device__ float g_W2T   [HID*HID];
__device__ float g_WselfT[EMB*HID];
__device__ float g_WneighT[HID*HID];
__device__ float g_relb2 [NEDGE*HID];
__device__ float g_neigh [ (size_t)NB*HID ];

// ------------------------------------------------------------------
// prep: transpose weights into [K][N] layout (coalesced B-tile rows)
// ------------------------------------------------------------------
__global__ void prep_transpose(const float* __restrict__ Wsrc, const float* __restrict__ Wdst,
                               const float* __restrict__ W2,   const float* __restrict__ Wself,
                               const float* __restrict__ Wneigh) {
    int i = blockIdx.x * blockDim.x + threadIdx.x;
    if (i < EMB*HID) {
        int k = i / HID, n = i % HID;
        g_WsrcT[i]  = Wsrc [n*EMB + k];
        g_WdstT[i]  = Wdst [n*EMB + k];
        g_WselfT[i] = Wself[n*EMB + k];
    }
    if (i < HID*HID) {
        int k = i / HID, n = i % HID;
        g_W2T[i]     = W2    [n*HID + k];
        g_WneighT[i] = Wneigh[n*HID + k];
    }
}

// prep: relb2[r][n] = b2[n] + sum_k edge_emb[r,k] * edge_lin_w[n,k]
__global__ void prep_relb2(const float* __restrict__ edge_emb,
                           const float* __restrict__ edge_lin_w,
                           const float* __restrict__ b2) {
    int n = threadIdx.x;   // 256 threads, 1 block
    for (int r = 0; r < NEDGE; r++) {
        float s = b2[n];
        #pragma unroll 4
        for (int k = 0; k < EMB; k++)
            s = fmaf(edge_emb[r*EMB + k], edge_lin_w[n*EMB + k], s);
        g_relb2[r*HID + n] = s;
    }
}

// ------------------------------------------------------------------
// shared-memory GEMM building blocks
// acc[i][j] covers row m = ty*4+i, col n = tx*16+j
// ------------------------------------------------------------------
__device__ __forceinline__ void mma_chunk(const float* __restrict__ Asm, int kbase,
                                          const float* __restrict__ Bsm,
                                          float (&acc)[4][16], int ty, int tx) {
    #pragma unroll 8
    for (int kk = 0; kk < KC; kk++) {
        const float* ar = Asm + (kbase + kk)*APITCH + (ty << 2);
        float a0 = ar[0], a1 = ar[1], a2 = ar[2], a3 = ar[3];
        const float* br = Bsm + kk*BPITCH + (tx << 4);
        float4 b0 = *(const float4*)(br + 0);
        float4 b1 = *(const float4*)(br + 4);
        float4 b2 = *(const float4*)(br + 8);
        float4 b3 = *(const float4*)(br + 12);
        float bv[16] = {b0.x,b0.y,b0.z,b0.w, b1.x,b1.y,b1.z,b1.w,
                        b2.x,b2.y,b2.z,b2.w, b3.x,b3.y,b3.z,b3.w};
        #pragma unroll
        for (int j = 0; j < 16; j++) {
            acc[0][j] = fmaf(a0, bv[j], acc[0][j]);
            acc[1][j] = fmaf(a1, bv[j], acc[1][j]);
            acc[2][j] = fmaf(a2, bv[j], acc[2][j]);
            acc[3][j] = fmaf(a3, bv[j], acc[3][j]);
        }
    }
}

// load KC x 256 weight rows (already transposed, contiguous) into Bsm
__device__ __forceinline__ void load_B(float* Bsm, const float* __restrict__ WT,
                                       int k0, int tid) {
    int kk = tid >> 3;                  // 0..31
    int n0 = (tid & 7) << 5;            // 0,32,...,224
    const float4* s = (const float4*)(WT + (size_t)(k0 + kk)*HID + n0);
    float4*       d = (float4*)(Bsm + kk*BPITCH + n0);
    #pragma unroll
    for (int j = 0; j < 8; j++) d[j] = s[j];
}

// gather a full K=128 slab for one row into transposed Asm[k][m]
// (thread layout: m = tid & 63, kq = tid >> 6 covers k-range kq*32..+31)
__device__ __forceinline__ void load_A_rows(float* Asm, const float* __restrict__ rowPtr,
                                            int m, int kq) {
    #pragma unroll
    for (int j4 = 0; j4 < 8; j4++) {
        float4 v = ((const float4*)rowPtr)[(kq << 3) + j4];
        int k = (kq << 5) + (j4 << 2);
        Asm[(k+0)*APITCH + m] = v.x;
        Asm[(k+1)*APITCH + m] = v.y;
        Asm[(k+2)*APITCH + m] = v.z;
        Asm[(k+3)*APITCH + m] = v.w;
    }
}

// ------------------------------------------------------------------
// event kernel: per block 64 events (4 batch rows)
// acc = src_e@WsrcT + dst_e@WdstT + m1@W2T; epilogue adds relb2, relu,
// valid-mask, fanout-mean -> g_neigh
// ------------------------------------------------------------------
__global__ __launch_bounds__(256, 2)
void ev_kernel(const int* __restrict__ nbr_ev,
               const int* __restrict__ ev_st, const int* __restrict__ ev_dt,
               const int* __restrict__ ev_et,
               const int* __restrict__ ev_sid, const int* __restrict__ ev_did,
               const int* __restrict__ ev_ts,  const float* __restrict__ ev_w,
               const float* __restrict__ emb0, const float* __restrict__ emb1,
               const float* __restrict__ mlp_w1, const float* __restrict__ mlp_b1) {
    extern __shared__ float smem[];
    float* Asm  = smem;                      // EMB*APITCH
    float* Bsm  = Asm + EMB*APITCH;          // KC*BPITCH
    float* part = Bsm + KC*BPITCH;           // 16*HID

    __shared__ const float* s_srcP[MT];
    __shared__ const float* s_dstP[MT];
    __shared__ float s_ts[MT], s_lw[MT], s_val[MT];
    __shared__ int   s_rel[MT];
    __shared__ float s_w1a[HID], s_w1b[HID], s_b1[HID];

    int tid = threadIdx.x;
    int tx = tid & 15, ty = tid >> 4;

    if (tid < MT) {
        int ev = nbr_ev[blockIdx.x*MT + tid];
        int e  = ev < 0 ? 0 : ev;
        s_val[tid] = ev < 0 ? 0.f : 1.f;
        s_srcP[tid] = (ev_st[e] == 0 ? emb0 : emb1) + (size_t)ev_sid[e]*EMB;
        s_dstP[tid] = (ev_dt[e] == 0 ? emb0 : emb1) + (size_t)ev_did[e]*EMB;
        s_rel[tid]  = ev_et[e];
        s_ts[tid]   = (float)ev_ts[e] / 1000000.0f;
        s_lw[tid]   = log1pf(ev_w[e]);
    }
    s_w1a[tid] = mlp_w1[tid*2 + 0];
    s_w1b[tid] = mlp_w1[tid*2 + 1];
    s_b1[tid]  = mlp_b1[tid];
    __syncthreads();

    float acc[4][16];
    #pragma unroll
    for (int i = 0; i < 4; i++)
        #pragma unroll
        for (int j = 0; j < 16; j++) acc[i][j] = 0.f;

    int m = tid & 63, kq = tid >> 6;

    // --- segment 1: src embedding projection (K=128) ---
    load_A_rows(Asm, s_srcP[m], m, kq);
    __syncthreads();
    #pragma unroll 1
    for (int c = 0; c < 4; c++) {
        load_B(Bsm, g_WsrcT, c*KC, tid);
        __syncthreads();
        mma_chunk(Asm, c*KC, Bsm, acc, ty, tx);
        __syncthreads();
    }

    // --- segment 2: dst embedding projection (K=128) ---
    load_A_rows(Asm, s_dstP[m], m, kq);
    __syncthreads();
    #pragma unroll 1
    for (int c = 0; c < 4; c++) {
        load_B(Bsm, g_WdstT, c*KC, tid);
        __syncthreads();
        mma_chunk(Asm, c*KC, Bsm, acc, ty, tx);
        __syncthreads();
    }

    // --- segment 3: MLP hidden @ W2T (K=256), A synthesized on the fly ---
    #pragma unroll 1
    for (int c = 0; c < 8; c++) {
        int k0 = c*KC;
        #pragma unroll
        for (int j = 0; j < 8; j++) {
            int k  = (kq << 3) + j;      // 0..31 within chunk
            int kg = k0 + k;
            float v = fmaf(s_ts[m], s_w1a[kg], fmaf(s_lw[m], s_w1b[kg], s_b1[kg]));
            Asm[k*APITCH + m] = fmaxf(v, 0.f);
        }
        load_B(Bsm, g_W2T, k0, tid);
        __syncthreads();
        mma_chunk(Asm, 0, Bsm, acc, ty, tx);
        __syncthreads();
    }

    // --- epilogue: + relb2[rel], relu, valid mask, mean over fanout ---
    #pragma unroll
    for (int j = 0; j < 16; j++) {
        int n = (tx << 4) + j;
        float s = 0.f;
        #pragma unroll
        for (int i = 0; i < 4; i++) {
            int mm = (ty << 2) + i;      // all 4 rows belong to batch row ty>>2
            float h = acc[i][j] + g_relb2[s_rel[mm]*HID + n];
            s += fmaxf(h, 0.f) * s_val[mm];
        }
        part[ty*HID + n] = s;
    }
    __syncthreads();
    for (int idx = tid; idx < 4*HID; idx += 256) {
        int rr = idx >> 8, n = idx & 255;
        float v = (part[(rr*4+0)*HID + n] + part[(rr*4+1)*HID + n] +
                   part[(rr*4+2)*HID + n] + part[(rr*4+3)*HID + n]) * 0.0625f;
        g_neigh[(size_t)(blockIdx.x*4 + rr)*HID + n] = v;
    }
}

// ------------------------------------------------------------------
// output kernel: out = relu(self_e@WselfT + neigh@WneighT), 64 rows/block
// ------------------------------------------------------------------
__global__ __launch_bounds__(256, 2)
void out_kernel(const int* __restrict__ node_ids,
                const float* __restrict__ emb0,
                float* __restrict__ out) {
    extern __shared__ float smem[];
    float* Asm = smem;
    float* Bsm = Asm + EMB*APITCH;
    __shared__ const float* s_rowP[MT];

    int tid = threadIdx.x;
    int tx = tid & 15, ty = tid >> 4;
    if (tid < MT)
        s_rowP[tid] = emb0 + (size_t)node_ids[blockIdx.x*MT + tid]*EMB;
    __syncthreads();

    float acc[4][16];
    #pragma unroll
    for (int i = 0; i < 4; i++)
        #pragma unroll
        for (int j = 0; j < 16; j++) acc[i][j] = 0.f;

    int m = tid & 63, kq = tid >> 6;

    // self projection (K=128)
    load_A_rows(Asm, s_rowP[m], m, kq);
    __syncthreads();
    #pragma unroll 1
    for (int c = 0; c < 4; c++) {
        load_B(Bsm, g_WselfT, c*KC, tid);
        __syncthreads();
        mma_chunk(Asm, c*KC, Bsm, acc, ty, tx);
        __syncthreads();
    }

    // neigh projection (K=256) in two 128-halves
    const float* np = g_neigh + (size_t)(blockIdx.x*MT + m)*HID;
    #pragma unroll 1
    for (int h = 0; h < 2; h++) {
        load_A_rows(Asm, np + h*EMB, m, kq);
        __syncthreads();
        #pragma unroll 1
        for (int c = 0; c < 4; c++) {
            load_B(Bsm, g_WneighT, h*EMB + c*KC, tid);
            __syncthreads();
            mma_chunk(Asm, c*KC, Bsm, acc, ty, tx);
            __syncthreads();
        }
    }

    // relu + write
    #pragma unroll
    for (int i = 0; i < 4; i++) {
        int row = blockIdx.x*MT + (ty << 2) + i;
        float4* dst = (float4*)(out + (size_t)row*HID + (tx << 4));
        #pragma unroll
        for (int q = 0; q < 4; q++) {
            dst[q] = make_float4(fmaxf(acc[i][q*4+0], 0.f),
                                 fmaxf(acc[i][q*4+1], 0.f),
                                 fmaxf(acc[i][q*4+2], 0.f),
                                 fmaxf(acc[i][q*4+3], 0.f));
        }
    }
}

// ------------------------------------------------------------------
extern "C" void kernel_launch(void* const* d_in, const int* in_sizes, int n_in,
                              void* d_out, int out_size) {
    const int*   node_ids = (const int*)d_in[0];
    const int*   nbr_ev   = (const int*)d_in[1];
    const int*   ev_st    = (const int*)d_in[2];
    const int*   ev_dt    = (const int*)d_in[3];
    const int*   ev_et    = (const int*)d_in[4];
    const int*   ev_sid   = (const int*)d_in[5];
    const int*   ev_did   = (const int*)d_in[6];
    const int*   ev_ts    = (const int*)d_in[7];
    const float* ev_w     = (const float*)d_in[8];
    const float* emb0     = (const float*)d_in[9];
    const float* emb1     = (const float*)d_in[10];
    const float* edge_emb = (const float*)d_in[11];
    const float* edge_lin = (const float*)d_in[12];
    const float* mlp_w1   = (const float*)d_in[13];
    const float* mlp_b1   = (const float*)d_in[14];
    const float* mlp_w2   = (const float*)d_in[15];
    const float* mlp_b2   = (const float*)d_in[16];
    const float* wsrc     = (const float*)d_in[17];
    const float* wdst     = (const float*)d_in[18];
    const float* wself    = (const float*)d_in[19];
    const float* wneigh   = (const float*)d_in[20];
    float* out = (float*)d_out;

    size_t smem2 = (size_t)(EMB*APITCH + KC*BPITCH + 16*HID) * sizeof(float);
    size_t smem3 = (size_t)(EMB*APITCH + KC*BPITCH) * sizeof(float);
    cudaFuncSetAttribute(ev_kernel,  cudaFuncAttributeMaxDynamicSharedMemorySize, (int)smem2);
    cudaFuncSetAttribute(out_kernel, cudaFuncAttributeMaxDynamicSharedMemorySize, (int)smem3);

    prep_transpose<<<(HID*HID + 255)/256, 256>>>(wsrc, wdst, mlp_w2, wself, wneigh);
    prep_relb2<<<1, 256>>>(edge_emb, edge_lin, mlp_b2);
    ev_kernel<<<NB*FANOUT/MT, 256, smem2>>>(nbr_ev, ev_st, ev_dt, ev_et, ev_sid, ev_did,
                                            ev_ts, ev_w, emb0, emb1, mlp_w1, mlp_b1);
    out_kernel<<<NB/MT, 256, smem3>>>(node_ids, emb0, out);
}

// round 3
// speedup vs baseline: 3.6202x; 3.6202x over previous
#include <cuda_runtime.h>
#include <math.h>
#include <stdint.h>

#define NB      16384
#define FANOUT  16
#define BE      (NB*FANOUT)
#define EMB     128
#define HID     256
#define NEDGE   16

#define BM      128      // rows per block
#define BN      128      // cols per block (grid.y = 2)
#define KC      32       // k-chunk
#define AP      36       // A smem pitch (floats): banks (4r+c) conflict-free
#define BP      136      // B smem pitch (floats): banks (8c+n) conflict-free
#define RBP     130      // relb2 slice pitch

// ---- persistent scratch (no allocations allowed) ----
__device__ float g_WsrcT_h[EMB*HID],  g_WsrcT_l[EMB*HID];
__device__ float g_WdstT_h[EMB*HID],  g_WdstT_l[EMB*HID];
__device__ float g_WselfT_h[EMB*HID], g_WselfT_l[EMB*HID];
__device__ float g_W2T_h[HID*HID],    g_W2T_l[HID*HID];
__device__ float g_WneighT_h[HID*HID],g_WneighT_l[HID*HID];
__device__ float g_relb2[NEDGE*HID];
__device__ float g_neigh[(size_t)NB*HID];

// ------------------------------------------------------------------
__device__ __forceinline__ float tf32_rna(float x) {
    uint32_t r;
    asm("cvt.rna.tf32.f32 %0, %1;" : "=r"(r) : "f"(x));
    return __uint_as_float(r);
}
__device__ __forceinline__ void split2(float x, float& h, float& l) {
    h = tf32_rna(x);
    l = tf32_rna(x - h);
}
__device__ __forceinline__ void mma8(float* d, const float* a, const float* b) {
    asm volatile("mma.sync.aligned.m16n8k8.row.col.f32.tf32.tf32.f32 "
        "{%0,%1,%2,%3},{%4,%5,%6,%7},{%8,%9},{%0,%1,%2,%3};"
        : "+f"(d[0]), "+f"(d[1]), "+f"(d[2]), "+f"(d[3])
        : "r"(__float_as_uint(a[0])), "r"(__float_as_uint(a[1])),
          "r"(__float_as_uint(a[2])), "r"(__float_as_uint(a[3])),
          "r"(__float_as_uint(b[0])), "r"(__float_as_uint(b[1])));
}

// ------------------------------------------------------------------
// prep: transpose + hi/lo split of weights into [K][N] layout
// ------------------------------------------------------------------
__global__ void prep_split(const float* __restrict__ Wsrc, const float* __restrict__ Wdst,
                           const float* __restrict__ W2,   const float* __restrict__ Wself,
                           const float* __restrict__ Wneigh) {
    int i = blockIdx.x * blockDim.x + threadIdx.x;
    if (i < EMB*HID) {
        int k = i / HID, n = i % HID;
        float h, l;
        split2(Wsrc [n*EMB + k], h, l); g_WsrcT_h [i] = h; g_WsrcT_l [i] = l;
        split2(Wdst [n*EMB + k], h, l); g_WdstT_h [i] = h; g_WdstT_l [i] = l;
        split2(Wself[n*EMB + k], h, l); g_WselfT_h[i] = h; g_WselfT_l[i] = l;
    }
    if (i < HID*HID) {
        int k = i / HID, n = i % HID;
        float h, l;
        split2(W2    [n*HID + k], h, l); g_W2T_h    [i] = h; g_W2T_l    [i] = l;
        split2(Wneigh[n*HID + k], h, l); g_WneighT_h[i] = h; g_WneighT_l[i] = l;
    }
}

// relb2[r][n] = b2[n] + edge_emb[r,:]·edge_lin_w[n,:]  (fp32, tiny)
__global__ void prep_relb2(const float* __restrict__ edge_emb,
                           const float* __restrict__ edge_lin_w,
                           const float* __restrict__ b2) {
    int n = threadIdx.x;
    for (int r = 0; r < NEDGE; r++) {
        float s = b2[n];
        #pragma unroll 4
        for (int k = 0; k < EMB; k++)
            s = fmaf(edge_emb[r*EMB + k], edge_lin_w[n*EMB + k], s);
        g_relb2[r*HID + n] = s;
    }
}

// ------------------------------------------------------------------
// producers
// ------------------------------------------------------------------
// gather + split 128 rows x 32 k of A into Ah/Al (row-major, pitch AP)
__device__ __forceinline__ void stageA(float* Ah, float* Al,
                                       const float* const* ptrs, int k0, int tid) {
    int m  = tid >> 1;
    int kb = (tid & 1) << 4;
    const float4* p = (const float4*)(ptrs[m] + k0 + kb);
    float* dh = Ah + m*AP + kb;
    float* dl = Al + m*AP + kb;
    #pragma unroll
    for (int j = 0; j < 4; j++) {
        float4 v = p[j];
        float4 h, l;
        split2(v.x, h.x, l.x); split2(v.y, h.y, l.y);
        split2(v.z, h.z, l.z); split2(v.w, h.w, l.w);
        *(float4*)(dh + 4*j) = h;
        *(float4*)(dl + 4*j) = l;
    }
}

// copy pre-split weight chunk [KC][BN] into Bh/Bl (k-major, pitch BP)
__device__ __forceinline__ void stageB(float* Bh, float* Bl,
                                       const float* __restrict__ WTh,
                                       const float* __restrict__ WTl,
                                       int k0, int colbase, int tid) {
    int k  = tid >> 3;
    int n0 = (tid & 7) << 2;
    const float* sh = WTh + (size_t)(k0 + k)*HID + colbase;
    const float* sl = WTl + (size_t)(k0 + k)*HID + colbase;
    float* dh = Bh + k*BP;
    float* dl = Bl + k*BP;
    #pragma unroll
    for (int j = 0; j < 4; j++) {
        int n = n0 + 32*j;
        *(float4*)(dh + n) = *(const float4*)(sh + n);
        *(float4*)(dl + n) = *(const float4*)(sl + n);
    }
}

// ------------------------------------------------------------------
// warp mma over one KC=32 chunk; 3xTF32 compensated
// ------------------------------------------------------------------
__device__ __forceinline__ void mma_chunk(const float* __restrict__ Ah,
                                          const float* __restrict__ Al,
                                          const float* __restrict__ Bh,
                                          const float* __restrict__ Bl,
                                          float (&acc)[2][8][4],
                                          int wm, int wn, int lane) {
    int r0 = wm*32 + (lane >> 2);
    int c  = lane & 3;
    int nb = wn*64 + (lane >> 2);
    #pragma unroll
    for (int kk = 0; kk < KC; kk += 8) {
        float ah[2][4], al[2][4];
        #pragma unroll
        for (int mf = 0; mf < 2; mf++) {
            const float* bh_ = Ah + (r0 + mf*16)*AP + kk + c;
            ah[mf][0] = bh_[0];      ah[mf][1] = bh_[8*AP];
            ah[mf][2] = bh_[4];      ah[mf][3] = bh_[8*AP + 4];
            const float* bl_ = Al + (r0 + mf*16)*AP + kk + c;
            al[mf][0] = bl_[0];      al[mf][1] = bl_[8*AP];
            al[mf][2] = bl_[4];      al[mf][3] = bl_[8*AP + 4];
        }
        #pragma unroll
        for (int nf = 0; nf < 8; nf++) {
            const float* pb = Bh + (kk + c)*BP + nb + nf*8;
            float bh[2] = { pb[0], pb[4*BP] };
            const float* pl = Bl + (kk + c)*BP + nb + nf*8;
            float bl[2] = { pl[0], pl[4*BP] };
            #pragma unroll
            for (int mf = 0; mf < 2; mf++) {
                mma8(acc[mf][nf], ah[mf], bh);
                mma8(acc[mf][nf], al[mf], bh);
                mma8(acc[mf][nf], ah[mf], bl);
            }
        }
    }
}

// ------------------------------------------------------------------
// event kernel
// ------------------------------------------------------------------
__global__ __launch_bounds__(256, 2)
void ev_kernel(const int* __restrict__ nbr_ev,
               const int* __restrict__ ev_st, const int* __restrict__ ev_dt,
               const int* __restrict__ ev_et,
               const int* __restrict__ ev_sid, const int* __restrict__ ev_did,
               const int* __restrict__ ev_ts,  const float* __restrict__ ev_w,
               const float* __restrict__ emb0, const float* __restrict__ emb1,
               const float* __restrict__ mlp_w1, const float* __restrict__ mlp_b1) {
    extern __shared__ float smem[];
    float* Ah = smem;                 // BM*AP
    float* Al = Ah + BM*AP;
    float* Bh = Al + BM*AP;           // KC*BP
    float* Bl = Bh + KC*BP;
    float* rb = Bl + KC*BP;           // NEDGE*RBP

    __shared__ const float* s_srcP[BM];
    __shared__ const float* s_dstP[BM];
    __shared__ float s_ts[BM], s_lw[BM], s_val[BM];
    __shared__ int   s_rel[BM];
    __shared__ float s_w1a[HID], s_w1b[HID], s_b1[HID];

    int tid  = threadIdx.x;
    int lane = tid & 31;
    int w    = tid >> 5;
    int wm   = w & 3, wn = w >> 2;
    int colbase = blockIdx.y * BN;

    if (tid < BM) {
        int ev = nbr_ev[blockIdx.x*BM + tid];
        int e  = ev < 0 ? 0 : ev;
        s_val[tid] = ev < 0 ? 0.f : 1.f;
        s_srcP[tid] = (ev_st[e] == 0 ? emb0 : emb1) + (size_t)ev_sid[e]*EMB;
        s_dstP[tid] = (ev_dt[e] == 0 ? emb0 : emb1) + (size_t)ev_did[e]*EMB;
        s_rel[tid]  = ev_et[e];
        s_ts[tid]   = (float)ev_ts[e] / 1000000.0f;
        s_lw[tid]   = log1pf(ev_w[e]);
    }
    s_w1a[tid] = mlp_w1[tid*2 + 0];
    s_w1b[tid] = mlp_w1[tid*2 + 1];
    s_b1[tid]  = mlp_b1[tid];
    for (int idx = tid; idx < NEDGE*BN; idx += 256) {
        int r = idx >> 7, cc = idx & 127;
        rb[r*RBP + cc] = g_relb2[r*HID + colbase + cc];
    }
    __syncthreads();

    float acc[2][8][4];
    #pragma unroll
    for (int a = 0; a < 2; a++)
        #pragma unroll
        for (int b = 0; b < 8; b++)
            #pragma unroll
            for (int q = 0; q < 4; q++) acc[a][b][q] = 0.f;

    // --- segment 1: src embedding (K=128) ---
    #pragma unroll 1
    for (int ch = 0; ch < 4; ch++) {
        stageA(Ah, Al, s_srcP, ch*KC, tid);
        stageB(Bh, Bl, g_WsrcT_h, g_WsrcT_l, ch*KC, colbase, tid);
        __syncthreads();
        mma_chunk(Ah, Al, Bh, Bl, acc, wm, wn, lane);
        __syncthreads();
    }
    // --- segment 2: dst embedding (K=128) ---
    #pragma unroll 1
    for (int ch = 0; ch < 4; ch++) {
        stageA(Ah, Al, s_dstP, ch*KC, tid);
        stageB(Bh, Bl, g_WdstT_h, g_WdstT_l, ch*KC, colbase, tid);
        __syncthreads();
        mma_chunk(Ah, Al, Bh, Bl, acc, wm, wn, lane);
        __syncthreads();
    }
    // --- segment 3: mlp hidden @ W2 (K=256), A synthesized on the fly ---
    #pragma unroll 1
    for (int ch = 0; ch < 8; ch++) {
        int k0 = ch*KC;
        {
            int m  = tid >> 1;
            int kb = (tid & 1) << 4;
            float ts = s_ts[m], lw = s_lw[m];
            float* dh = Ah + m*AP + kb;
            float* dl = Al + m*AP + kb;
            #pragma unroll
            for (int j = 0; j < 4; j++) {
                float4 h, l;
                #pragma unroll
                for (int e = 0; e < 4; e++) {
                    int kg = k0 + kb + 4*j + e;
                    float v = fmaf(ts, s_w1a[kg], fmaf(lw, s_w1b[kg], s_b1[kg]));
                    v = fmaxf(v, 0.f);
                    float hh, ll; split2(v, hh, ll);
                    ((float*)&h)[e] = hh; ((float*)&l)[e] = ll;
                }
                *(float4*)(dh + 4*j) = h;
                *(float4*)(dl + 4*j) = l;
            }
        }
        stageB(Bh, Bl, g_W2T_h, g_W2T_l, k0, colbase, tid);
        __syncthreads();
        mma_chunk(Ah, Al, Bh, Bl, acc, wm, wn, lane);
        __syncthreads();
    }

    // --- epilogue: + relb2, relu, mask, fanout-mean via shfl ---
    #pragma unroll
    for (int mf = 0; mf < 2; mf++) {
        int r0 = wm*32 + mf*16 + (lane >> 2);
        int r1 = r0 + 8;
        float v0 = s_val[r0], v1 = s_val[r1];
        int rel0 = s_rel[r0], rel1 = s_rel[r1];
        int brow = blockIdx.x*8 + wm*2 + mf;
        #pragma unroll
        for (int nf = 0; nf < 8; nf++) {
            int cl = wn*64 + nf*8 + 2*(lane & 3);
            float p0 = fmaxf(acc[mf][nf][0] + rb[rel0*RBP + cl],     0.f)*v0
                     + fmaxf(acc[mf][nf][2] + rb[rel1*RBP + cl],     0.f)*v1;
            float p1 = fmaxf(acc[mf][nf][1] + rb[rel0*RBP + cl + 1], 0.f)*v0
                     + fmaxf(acc[mf][nf][3] + rb[rel1*RBP + cl + 1], 0.f)*v1;
            p0 += __shfl_xor_sync(0xffffffffu, p0, 4);
            p0 += __shfl_xor_sync(0xffffffffu, p0, 8);
            p0 += __shfl_xor_sync(0xffffffffu, p0, 16);
            p1 += __shfl_xor_sync(0xffffffffu, p1, 4);
            p1 += __shfl_xor_sync(0xffffffffu, p1, 8);
            p1 += __shfl_xor_sync(0xffffffffu, p1, 16);
            if ((lane >> 2) == 0) {
                int gc = colbase + cl;
                *(float2*)&g_neigh[(size_t)brow*HID + gc] =
                    make_float2(p0 * 0.0625f, p1 * 0.0625f);
            }
        }
    }
}

// ------------------------------------------------------------------
// output kernel: out = relu(self@WselfT + neigh@WneighT)
// ------------------------------------------------------------------
__global__ __launch_bounds__(256, 2)
void out_kernel(const int* __restrict__ node_ids,
                const float* __restrict__ emb0,
                float* __restrict__ out) {
    extern __shared__ float smem[];
    float* Ah = smem;
    float* Al = Ah + BM*AP;
    float* Bh = Al + BM*AP;
    float* Bl = Bh + KC*BP;

    __shared__ const float* s_selfP[BM];
    __shared__ const float* s_neighP[BM];

    int tid  = threadIdx.x;
    int lane = tid & 31;
    int w    = tid >> 5;
    int wm   = w & 3, wn = w >> 2;
    int colbase = blockIdx.y * BN;
    int rowbase = blockIdx.x * BM;

    if (tid < BM) {
        s_selfP[tid]  = emb0 + (size_t)node_ids[rowbase + tid]*EMB;
        s_neighP[tid] = g_neigh + (size_t)(rowbase + tid)*HID;
    }
    __syncthreads();

    float acc[2][8][4];
    #pragma unroll
    for (int a = 0; a < 2; a++)
        #pragma unroll
        for (int b = 0; b < 8; b++)
            #pragma unroll
            for (int q = 0; q < 4; q++) acc[a][b][q] = 0.f;

    // self projection (K=128)
    #pragma unroll 1
    for (int ch = 0; ch < 4; ch++) {
        stageA(Ah, Al, s_selfP, ch*KC, tid);
        stageB(Bh, Bl, g_WselfT_h, g_WselfT_l, ch*KC, colbase, tid);
        __syncthreads();
        mma_chunk(Ah, Al, Bh, Bl, acc, wm, wn, lane);
        __syncthreads();
    }
    // neigh projection (K=256)
    #pragma unroll 1
    for (int ch = 0; ch < 8; ch++) {
        stageA(Ah, Al, s_neighP, ch*KC, tid);
        stageB(Bh, Bl, g_WneighT_h, g_WneighT_l, ch*KC, colbase, tid);
        __syncthreads();
        mma_chunk(Ah, Al, Bh, Bl, acc, wm, wn, lane);
        __syncthreads();
    }

    // relu + write
    #pragma unroll
    for (int mf = 0; mf < 2; mf++) {
        int r0 = rowbase + wm*32 + mf*16 + (lane >> 2);
        int r1 = r0 + 8;
        #pragma unroll
        for (int nf = 0; nf < 8; nf++) {
            int gc = colbase + wn*64 + nf*8 + 2*(lane & 3);
            *(float2*)&out[(size_t)r0*HID + gc] =
                make_float2(fmaxf(acc[mf][nf][0], 0.f), fmaxf(acc[mf][nf][1], 0.f));
            *(float2*)&out[(size_t)r1*HID + gc] =
                make_float2(fmaxf(acc[mf][nf][2], 0.f), fmaxf(acc[mf][nf][3], 0.f));
        }
    }
}

// ------------------------------------------------------------------
extern "C" void kernel_launch(void* const* d_in, const int* in_sizes, int n_in,
                              void* d_out, int out_size) {
    const int*   node_ids = (const int*)d_in[0];
    const int*   nbr_ev   = (const int*)d_in[1];
    const int*   ev_st    = (const int*)d_in[2];
    const int*   ev_dt    = (const int*)d_in[3];
    const int*   ev_et    = (const int*)d_in[4];
    const int*   ev_sid   = (const int*)d_in[5];
    const int*   ev_did   = (const int*)d_in[6];
    const int*   ev_ts    = (const int*)d_in[7];
    const float* ev_w     = (const float*)d_in[8];
    const float* emb0     = (const float*)d_in[9];
    const float* emb1     = (const float*)d_in[10];
    const float* edge_emb = (const float*)d_in[11];
    const float* edge_lin = (const float*)d_in[12];
    const float* mlp_w1   = (const float*)d_in[13];
    const float* mlp_b1   = (const float*)d_in[14];
    const float* mlp_w2   = (const float*)d_in[15];
    const float* mlp_b2   = (const float*)d_in[16];
    const float* wsrc     = (const float*)d_in[17];
    const float* wdst     = (const float*)d_in[18];
    const float* wself    = (const float*)d_in[19];
    const float* wneigh   = (const float*)d_in[20];
    float* out = (float*)d_out;

    size_t smem_ev  = (size_t)(2*BM*AP + 2*KC*BP + NEDGE*RBP) * sizeof(float);
    size_t smem_out = (size_t)(2*BM*AP + 2*KC*BP) * sizeof(float);
    cudaFuncSetAttribute(ev_kernel,  cudaFuncAttributeMaxDynamicSharedMemorySize, (int)smem_ev);
    cudaFuncSetAttribute(out_kernel, cudaFuncAttributeMaxDynamicSharedMemorySize, (int)smem_out);

    prep_split<<<(HID*HID + 255)/256, 256>>>(wsrc, wdst, mlp_w2, wself, wneigh);
    prep_relb2<<<1, 256>>>(edge_emb, edge_lin, mlp_b2);

    dim3 gev(BE/BM, 2);
    ev_kernel<<<gev, 256, smem_ev>>>(nbr_ev, ev_st, ev_dt, ev_et, ev_sid, ev_did,
                                     ev_ts, ev_w, emb0, emb1, mlp_w1, mlp_b1);
    dim3 gout(NB/BM, 2);
    out_kernel<<<gout, 256, smem_out>>>(node_ids, emb0, out);
}